// round 14
// baseline (speedup 1.0000x reference)
#include <cuda_runtime.h>
#include <cuda_bf16.h>
#include <cstdint>
#include <cstddef>

#define NN 100000
#define EMAX 1600000
#define TILES 782          // ceil(NN/128)

// ---- static device scratch (zero-initialized at module load) ----
__device__ int      g_count[NN];
__device__ int      g_offsets[NN + 1];
__device__ int      g_cursor[NN];
__device__ int      g_sorted[EMAX];
__device__ uint2    g_xh[(size_t)NN * 32];     // bf16 gather plane for x
__device__ uint2    g_h1h[(size_t)NN * 32];    // bf16 gather plane for h1
__device__ float    g_mean[(size_t)NN * 128];
__device__ float    g_h1[(size_t)NN * 128];
__device__ float    g_h2[(size_t)NN * 128];
__device__ uint32_t g_bp1[32768];   // fragment-order packed B (hi/lo bf16x2), 128KB
__device__ uint32_t g_bp2[32768];

// ===================== hist (+ fused x->bf16 plane) =====================
// g_count is zero at entry: zero-initialized at load, re-zeroed by scan each run.
__global__ void hist_tobf16_kernel(const int* __restrict__ dst, int E,
                                   const float4* __restrict__ x4, uint2* __restrict__ xh, int n4) {
    int stride = gridDim.x * blockDim.x;
    for (int e = blockIdx.x * blockDim.x + threadIdx.x; e < E; e += stride)
        atomicAdd(&g_count[dst[e]], 1);
    for (int i = blockIdx.x * blockDim.x + threadIdx.x; i < n4; i += stride) {
        float4 v = x4[i];
        __nv_bfloat162 a = __float22bfloat162_rn(make_float2(v.x, v.y));
        __nv_bfloat162 b = __float22bfloat162_rn(make_float2(v.z, v.w));
        xh[i] = make_uint2(*(uint32_t*)&a, *(uint32_t*)&b);
    }
}

// ===================== single-block coalesced serial-chunk scan =====================
// (R1's proven scan; also re-zeros g_count for the next graph replay)
__global__ void scan_single_kernel() {
    __shared__ int ws[32];
    int t = threadIdx.x, lane = t & 31, w = t >> 5;
    int carry = 0;
    for (int base = 0; base < NN; base += 1024) {
        int i = base + t;
        int v = (i < NN) ? g_count[i] : 0;
        int x = v;
        #pragma unroll
        for (int o = 1; o < 32; o <<= 1) { int y = __shfl_up_sync(~0u, x, o); if (lane >= o) x += y; }
        if (lane == 31) ws[w] = x;
        __syncthreads();
        if (w == 0) {
            int s = ws[lane];
            #pragma unroll
            for (int o = 1; o < 32; o <<= 1) { int y = __shfl_up_sync(~0u, s, o); if (lane >= o) s += y; }
            ws[lane] = s;
        }
        __syncthreads();
        int excl = carry + (w ? ws[w - 1] : 0) + x - v;
        if (i < NN) { g_offsets[i] = excl; g_cursor[i] = excl; g_count[i] = 0; }
        int total = ws[31];
        __syncthreads();
        carry += total;
    }
    if (t == 0) g_offsets[NN] = carry;
}

__global__ void scatter_kernel(const int* __restrict__ src, const int* __restrict__ dst, int E) {
    for (int e = blockIdx.x * blockDim.x + threadIdx.x; e < E; e += gridDim.x * blockDim.x) {
        int d = dst[e];
        int pos = atomicAdd(&g_cursor[d], 1);
        g_sorted[pos] = src[e];
    }
}

// ===================== fp32 -> bf16 plane (h1) =====================
__global__ void tobf16_kernel(const float4* __restrict__ x4, uint2* __restrict__ xh, int n4) {
    int i = blockIdx.x * blockDim.x + threadIdx.x;
    if (i >= n4) return;
    float4 v = x4[i];
    __nv_bfloat162 a = __float22bfloat162_rn(make_float2(v.x, v.y));
    __nv_bfloat162 b = __float22bfloat162_rn(make_float2(v.z, v.w));
    xh[i] = make_uint2(*(uint32_t*)&a, *(uint32_t*)&b);
}

// ===================== B fragment pack (both layers, FULL N=128) =====================
__global__ void pack_both_kernel(const float* __restrict__ w1l, const float* __restrict__ w1r,
                                 const float* __restrict__ w2l, const float* __restrict__ w2r,
                                 uint32_t* __restrict__ bp1, uint32_t* __restrict__ bp2) {
    int gi = blockIdx.x * blockDim.x + threadIdx.x;
    if (gi >= 65536) return;
    const float* wl = (gi < 32768) ? w1l : w2l;
    const float* wr = (gi < 32768) ? w1r : w2r;
    uint32_t* bp = (gi < 32768) ? bp1 : bp2;
    int idx = gi & 32767;
    int j = idx & 3, lane = (idx >> 2) & 31, p = (idx >> 7) & 1;
    int nw = (idx >> 8) & 3, term = (idx >> 10) & 1, gk = idx >> 11;
    int nb = p * 2 + (j >> 1), reg = j & 1;
    int n = nw * 32 + nb * 8 + (lane >> 2);
    int k = gk * 16 + reg * 8 + 2 * (lane & 3);
    float v0 = (k < 128) ? wl[n * 128 + k] : wr[n * 128 + (k - 128)];
    float v1 = (k + 1 < 128) ? wl[n * 128 + k + 1] : wr[n * 128 + (k + 1 - 128)];
    __nv_bfloat162 h2 = __float22bfloat162_rn(make_float2(v0, v1));
    if (term == 0) {
        bp[idx] = *(uint32_t*)&h2;
    } else {
        float r0 = v0 - __low2float(h2);
        float r1 = v1 - __high2float(h2);
        __nv_bfloat162 l2 = __float22bfloat162_rn(make_float2(r0, r1));
        bp[idx] = *(uint32_t*)&l2;
    }
}

// ===================== aggregation: lane-parallel index fetch + shfl broadcast =====================
__global__ void agg_kernel(const uint2* __restrict__ xp, float4* __restrict__ out4) {
    int gw = (blockIdx.x * blockDim.x + threadIdx.x) >> 5;
    int lane = threadIdx.x & 31;
    if (gw >= NN) return;
    int beg = g_offsets[gw], end = g_offsets[gw + 1];
    float a0 = 0.f, a1 = 0.f, a2 = 0.f, a3 = 0.f;
    for (int p = beg; p < end; p += 32) {
        int n = end - p; if (n > 32) n = 32;
        // one coalesced load fetches up to 32 edge indices for the whole warp
        int idx = (p + lane < end) ? g_sorted[p + lane] : 0;
        int j = 0;
        for (; j + 4 <= n; j += 4) {
            int s0 = __shfl_sync(~0u, idx, j);
            int s1 = __shfl_sync(~0u, idx, j + 1);
            int s2 = __shfl_sync(~0u, idx, j + 2);
            int s3 = __shfl_sync(~0u, idx, j + 3);
            uint2 u0 = __ldg(&xp[(size_t)s0 * 32 + lane]);
            uint2 u1 = __ldg(&xp[(size_t)s1 * 32 + lane]);
            uint2 u2 = __ldg(&xp[(size_t)s2 * 32 + lane]);
            uint2 u3 = __ldg(&xp[(size_t)s3 * 32 + lane]);
            float2 f;
            f = __bfloat1622float2(*(__nv_bfloat162*)&u0.x); a0 += f.x; a1 += f.y;
            f = __bfloat1622float2(*(__nv_bfloat162*)&u0.y); a2 += f.x; a3 += f.y;
            f = __bfloat1622float2(*(__nv_bfloat162*)&u1.x); a0 += f.x; a1 += f.y;
            f = __bfloat1622float2(*(__nv_bfloat162*)&u1.y); a2 += f.x; a3 += f.y;
            f = __bfloat1622float2(*(__nv_bfloat162*)&u2.x); a0 += f.x; a1 += f.y;
            f = __bfloat1622float2(*(__nv_bfloat162*)&u2.y); a2 += f.x; a3 += f.y;
            f = __bfloat1622float2(*(__nv_bfloat162*)&u3.x); a0 += f.x; a1 += f.y;
            f = __bfloat1622float2(*(__nv_bfloat162*)&u3.y); a2 += f.x; a3 += f.y;
        }
        for (; j < n; j++) {
            int s = __shfl_sync(~0u, idx, j);
            uint2 u = __ldg(&xp[(size_t)s * 32 + lane]);
            float2 f;
            f = __bfloat1622float2(*(__nv_bfloat162*)&u.x); a0 += f.x; a1 += f.y;
            f = __bfloat1622float2(*(__nv_bfloat162*)&u.y); a2 += f.x; a3 += f.y;
        }
    }
    float inv = (end > beg) ? 1.0f / (float)(end - beg) : 0.0f;
    out4[(size_t)gw * 32 + lane] = make_float4(a0 * inv, a1 * inv, a2 * inv, a3 * inv);
}

// ===================== mma.sync GEMM (identical to R7 — known good) =====================
#define AROW 144
#define SM_AHI  0
#define SM_ALO  18432
#define SM_BIAS 36864
#define GEMM_SMEM 37376

__device__ __forceinline__ uint32_t smem_u32(const void* p) {
    uint32_t a;
    asm("{ .reg .u64 t; cvta.to.shared.u64 t, %1; cvt.u32.u64 %0, t; }" : "=r"(a) : "l"(p));
    return a;
}
__device__ __forceinline__ void ldm_x4(uint32_t* r, uint32_t addr) {
    asm volatile("ldmatrix.sync.aligned.m8n8.x4.shared.b16 {%0,%1,%2,%3}, [%4];"
                 : "=r"(r[0]), "=r"(r[1]), "=r"(r[2]), "=r"(r[3]) : "r"(addr));
}
__device__ __forceinline__ void mma_bf16(float* d, const uint32_t* a, uint32_t b0, uint32_t b1) {
    asm volatile("mma.sync.aligned.m16n8k16.row.col.f32.bf16.bf16.f32 "
                 "{%0,%1,%2,%3}, {%4,%5,%6,%7}, {%8,%9}, {%0,%1,%2,%3};"
                 : "+f"(d[0]), "+f"(d[1]), "+f"(d[2]), "+f"(d[3])
                 : "r"(a[0]), "r"(a[1]), "r"(a[2]), "r"(a[3]), "r"(b0), "r"(b1));
}

__global__ __launch_bounds__(256, 2) void gemm_mma_kernel(
    const float* __restrict__ A0, const float* __restrict__ A1,
    const uint32_t* __restrict__ Bp, const float* __restrict__ bias,
    float* __restrict__ C)
{
    extern __shared__ char smem[];
    uint32_t sb = smem_u32(smem);
    int t = threadIdx.x, wid = t >> 5, lane = t & 31;
    int mw = wid >> 2, nw = wid & 3;      // warp grid 2 x 4

    if (t < 128) ((float*)(smem + SM_BIAS))[t] = bias[t];

    int frow = t >> 1, fh = t & 1;
    int lrow = (lane & 7) + ((lane >> 3) & 1) * 8;
    int lkb  = (lane >> 4) * 16;
    const float* bsm = (const float*)(smem + SM_BIAS);
    const uint4* bfrag = (const uint4*)(Bp) + ((nw * 2) * 128 + lane * 4) / 4;

    for (int tile = blockIdx.x; tile < TILES; tile += gridDim.x) {
        float acc[4][4][4];
        #pragma unroll
        for (int m = 0; m < 4; m++)
            #pragma unroll
            for (int nb = 0; nb < 4; nb++)
                #pragma unroll
                for (int r = 0; r < 4; r++) acc[m][nb][r] = 0.f;

        int grow = tile * 128 + frow;
        bool rv = grow < NN;

        #pragma unroll 1
        for (int c = 0; c < 4; c++) {            // K chunks of 64
            __syncthreads();
            {
                const float* As = (c < 2) ? A0 : A1;
                const float4* ap = (const float4*)As + (size_t)grow * 32 + ((c & 1) * 16 + fh * 8);
                float4 v[8];
                if (rv) {
                    #pragma unroll
                    for (int i = 0; i < 8; i++) v[i] = __ldg(ap + i);
                } else {
                    #pragma unroll
                    for (int i = 0; i < 8; i++) v[i] = make_float4(0.f, 0.f, 0.f, 0.f);
                }
                const float* vf = (const float*)v;
                uint32_t hw[16], lw[16];
                #pragma unroll
                for (int i = 0; i < 16; i++) {
                    float f0 = vf[2 * i], f1 = vf[2 * i + 1];
                    __nv_bfloat162 h2 = __float22bfloat162_rn(make_float2(f0, f1));
                    float r0 = f0 - __low2float(h2);
                    float r1 = f1 - __high2float(h2);
                    __nv_bfloat162 l2 = __float22bfloat162_rn(make_float2(r0, r1));
                    hw[i] = *(uint32_t*)&h2;
                    lw[i] = *(uint32_t*)&l2;
                }
                char* hb = smem + SM_AHI + frow * AROW + fh * 64;
                char* lb = smem + SM_ALO + frow * AROW + fh * 64;
                #pragma unroll
                for (int q = 0; q < 4; q++) {
                    *(uint4*)(hb + q * 16) = make_uint4(hw[4*q], hw[4*q+1], hw[4*q+2], hw[4*q+3]);
                    *(uint4*)(lb + q * 16) = make_uint4(lw[4*q], lw[4*q+1], lw[4*q+2], lw[4*q+3]);
                }
            }
            __syncthreads();
            #pragma unroll
            for (int ks = 0; ks < 4; ks++) {
                int gk = c * 4 + ks;
                const uint4* bgk = bfrag + (size_t)gk * 512;
                uint4 bh0 = __ldg(bgk + 0);
                uint4 bh1 = __ldg(bgk + 32);
                uint4 bl0 = __ldg(bgk + 256);
                uint4 bl1 = __ldg(bgk + 288);
                uint32_t bh[4][2] = {{bh0.x, bh0.y}, {bh0.z, bh0.w}, {bh1.x, bh1.y}, {bh1.z, bh1.w}};
                uint32_t bl[4][2] = {{bl0.x, bl0.y}, {bl0.z, bl0.w}, {bl1.x, bl1.y}, {bl1.z, bl1.w}};
                #pragma unroll
                for (int m = 0; m < 4; m++) {
                    uint32_t ah[4], al[4];
                    uint32_t rbase = sb + (uint32_t)((mw * 64 + m * 16 + lrow) * AROW + ks * 32 + lkb);
                    ldm_x4(ah, rbase + SM_AHI);
                    ldm_x4(al, rbase + SM_ALO);
                    #pragma unroll
                    for (int nb = 0; nb < 4; nb++) {
                        mma_bf16(acc[m][nb], ah, bh[nb][0], bh[nb][1]);
                        mma_bf16(acc[m][nb], al, bh[nb][0], bh[nb][1]);
                        mma_bf16(acc[m][nb], ah, bl[nb][0], bl[nb][1]);
                    }
                }
            }
        }
        #pragma unroll
        for (int m = 0; m < 4; m++) {
            int orow0 = tile * 128 + mw * 64 + m * 16 + (lane >> 2);
            #pragma unroll
            for (int nb = 0; nb < 4; nb++) {
                int ocol = nw * 32 + nb * 8 + 2 * (lane & 3);
                float b0 = bsm[ocol], b1 = bsm[ocol + 1];
                if (orow0 < NN) {
                    float2 o = make_float2(fmaxf(acc[m][nb][0] + b0, 0.f),
                                           fmaxf(acc[m][nb][1] + b1, 0.f));
                    *(float2*)&C[(size_t)orow0 * 128 + ocol] = o;
                }
                if (orow0 + 8 < NN) {
                    float2 o = make_float2(fmaxf(acc[m][nb][2] + b0, 0.f),
                                           fmaxf(acc[m][nb][3] + b1, 0.f));
                    *(float2*)&C[(size_t)(orow0 + 8) * 128 + ocol] = o;
                }
            }
        }
    }
}

// ===================== output projection =====================
__global__ void outproj_kernel(const float4* __restrict__ h4, const float* __restrict__ wout,
                               const float* __restrict__ bout, float4* __restrict__ out, int N) {
    int gw = (blockIdx.x * blockDim.x + threadIdx.x) >> 5;
    int lane = threadIdx.x & 31;
    if (gw >= N) return;
    float4 v = h4[(size_t)gw * 32 + lane];
    const float4* w4 = (const float4*)wout;
    float acc[4];
    #pragma unroll
    for (int j = 0; j < 4; j++) {
        float4 w = __ldg(&w4[j * 32 + lane]);
        acc[j] = v.x * w.x + v.y * w.y + v.z * w.z + v.w * w.w;
    }
    #pragma unroll
    for (int j = 0; j < 4; j++)
        #pragma unroll
        for (int o = 16; o > 0; o >>= 1) acc[j] += __shfl_down_sync(~0u, acc[j], o);
    if (lane == 0)
        out[gw] = make_float4(acc[0] + bout[0], acc[1] + bout[1],
                              acc[2] + bout[2], acc[3] + bout[3]);
}

// ===================== launch =====================
extern "C" void kernel_launch(void* const* d_in, const int* in_sizes, int n_in,
                              void* d_out, int out_size) {
    const float* x    = (const float*)d_in[0];
    const int*   ei   = (const int*)d_in[1];
    const float* w1l  = (const float*)d_in[2];
    const float* b1l  = (const float*)d_in[3];
    const float* w1r  = (const float*)d_in[4];
    const float* w2l  = (const float*)d_in[5];
    const float* b2l  = (const float*)d_in[6];
    const float* w2r  = (const float*)d_in[7];
    const float* wout = (const float*)d_in[8];
    const float* bout = (const float*)d_in[9];
    float* out = (float*)d_out;

    int E = in_sizes[1] / 2;
    const int* src = ei;
    const int* dst = ei + E;

    uint2 *xh, *h1h;
    float *mean, *h1, *h2;
    uint32_t *bp1, *bp2;
    cudaGetSymbolAddress((void**)&xh, g_xh);
    cudaGetSymbolAddress((void**)&h1h, g_h1h);
    cudaGetSymbolAddress((void**)&mean, g_mean);
    cudaGetSymbolAddress((void**)&h1, g_h1);
    cudaGetSymbolAddress((void**)&h2, g_h2);
    cudaGetSymbolAddress((void**)&bp1, g_bp1);
    cudaGetSymbolAddress((void**)&bp2, g_bp2);

    cudaFuncSetAttribute(gemm_mma_kernel, cudaFuncAttributeMaxDynamicSharedMemorySize, GEMM_SMEM);

    int n4 = NN * 32;
    int aggBlocks = (NN * 32 + 255) / 256;

    // launch 0: hist (g_count pre-zeroed) + fused x->bf16 plane
    hist_tobf16_kernel<<<2048, 256>>>(dst, E, (const float4*)x, xh, n4);
    // launch 1: single-kernel coalesced scan (re-zeros g_count for next replay)
    scan_single_kernel<<<1, 1024>>>();
    // launch 2: scatter
    scatter_kernel<<<2048, 256>>>(src, dst, E);
    // launch 3: layer-1 aggregation  <-- profiled by ncu
    agg_kernel<<<aggBlocks, 256>>>(xh, (float4*)mean);
    // launch 4: weight packs (both layers)
    pack_both_kernel<<<256, 256>>>(w1l, w1r, w2l, w2r, bp1, bp2);
    // layer 1 GEMM
    gemm_mma_kernel<<<296, 256, GEMM_SMEM>>>(mean, x, bp1, b1l, h1);
    // h1 -> bf16 gather plane
    tobf16_kernel<<<(n4 + 255) / 256, 256>>>((const float4*)h1, h1h, n4);
    // layer 2
    agg_kernel<<<aggBlocks, 256>>>(h1h, (float4*)mean);
    gemm_mma_kernel<<<296, 256, GEMM_SMEM>>>(mean, h1, bp2, b2l, h2);
    // output projection
    outproj_kernel<<<aggBlocks, 256>>>((const float4*)h2, wout, bout, (float4*)out, NN);
}

// round 15
// speedup vs baseline: 1.2854x; 1.2854x over previous
#include <cuda_runtime.h>
#include <cuda_bf16.h>
#include <cstdint>
#include <cstddef>

#define NN 100000
#define EMAX 1600000
#define TILES 782          // ceil(NN/128)

// ---- static device scratch (zero-initialized at module load) ----
__device__ int      g_count[NN];
__device__ int      g_offsets[NN + 1];
__device__ int      g_cursor[NN];
__device__ int      g_bsum[128];
__device__ int      g_sorted[EMAX];
__device__ uint2    g_xh[(size_t)NN * 32];     // bf16 gather plane for x
__device__ uint2    g_h1h[(size_t)NN * 32];    // bf16 gather plane for h1
__device__ float    g_mean[(size_t)NN * 128];
__device__ float    g_h1[(size_t)NN * 128];
__device__ uint32_t g_bp1[32768];   // fragment-order packed B (hi/lo bf16x2), 128KB
__device__ uint32_t g_bp2[32768];

// ===================== hist (+ fused x->bf16 plane) =====================
__global__ void hist_tobf16_kernel(const int* __restrict__ dst, int E,
                                   const float4* __restrict__ x4, uint2* __restrict__ xh, int n4) {
    int stride = gridDim.x * blockDim.x;
    for (int e = blockIdx.x * blockDim.x + threadIdx.x; e < E; e += stride)
        atomicAdd(&g_count[dst[e]], 1);
    for (int i = blockIdx.x * blockDim.x + threadIdx.x; i < n4; i += stride) {
        float4 v = x4[i];
        __nv_bfloat162 a = __float22bfloat162_rn(make_float2(v.x, v.y));
        __nv_bfloat162 b = __float22bfloat162_rn(make_float2(v.z, v.w));
        xh[i] = make_uint2(*(uint32_t*)&a, *(uint32_t*)&b);
    }
}

// ===================== 3-phase coalesced scan (measured ~8us) =====================
__global__ void scan_local_kernel() {
    __shared__ int ws[32];
    int i = blockIdx.x * 1024 + threadIdx.x;
    int lane = threadIdx.x & 31, w = threadIdx.x >> 5;
    int v = (i < NN) ? g_count[i] : 0;
    int x = v;
    #pragma unroll
    for (int o = 1; o < 32; o <<= 1) { int y = __shfl_up_sync(~0u, x, o); if (lane >= o) x += y; }
    if (lane == 31) ws[w] = x;
    __syncthreads();
    if (w == 0) {
        int s = ws[lane];
        #pragma unroll
        for (int o = 1; o < 32; o <<= 1) { int y = __shfl_up_sync(~0u, s, o); if (lane >= o) s += y; }
        ws[lane] = s;
    }
    __syncthreads();
    int excl = (w ? ws[w - 1] : 0) + x - v;
    if (i < NN) g_offsets[i] = excl;
    if (threadIdx.x == 0) g_bsum[blockIdx.x] = ws[31];
}
__global__ void scan_bsum_kernel(int nseg) {
    __shared__ int sh[4];
    int t = threadIdx.x, lane = t & 31, w = t >> 5;
    int v = (t < nseg) ? g_bsum[t] : 0;
    int x = v;
    #pragma unroll
    for (int o = 1; o < 32; o <<= 1) { int y = __shfl_up_sync(~0u, x, o); if (lane >= o) x += y; }
    if (lane == 31) sh[w] = x;
    __syncthreads();
    int add = 0;
    for (int j = 0; j < w; j++) add += sh[j];
    int incl = x + add;
    g_bsum[t] = incl - v;
    if (t == 127) g_offsets[NN] = incl;
}
// phase 3: add scanned block sums; ALSO re-zero g_count for the next graph replay
__global__ void scan_add_kernel() {
    int i = blockIdx.x * blockDim.x + threadIdx.x;
    if (i < NN) {
        int o = g_offsets[i] + g_bsum[i >> 10];
        g_offsets[i] = o;
        g_cursor[i] = o;
        g_count[i] = 0;
    }
}
__global__ void scatter_kernel(const int* __restrict__ src, const int* __restrict__ dst, int E) {
    for (int e = blockIdx.x * blockDim.x + threadIdx.x; e < E; e += gridDim.x * blockDim.x) {
        int d = dst[e];
        int pos = atomicAdd(&g_cursor[d], 1);
        g_sorted[pos] = src[e];
    }
}

// ===================== B fragment pack (both layers, FULL N=128) =====================
__global__ void pack_both_kernel(const float* __restrict__ w1l, const float* __restrict__ w1r,
                                 const float* __restrict__ w2l, const float* __restrict__ w2r,
                                 uint32_t* __restrict__ bp1, uint32_t* __restrict__ bp2) {
    int gi = blockIdx.x * blockDim.x + threadIdx.x;
    if (gi >= 65536) return;
    const float* wl = (gi < 32768) ? w1l : w2l;
    const float* wr = (gi < 32768) ? w1r : w2r;
    uint32_t* bp = (gi < 32768) ? bp1 : bp2;
    int idx = gi & 32767;
    int j = idx & 3, lane = (idx >> 2) & 31, p = (idx >> 7) & 1;
    int nw = (idx >> 8) & 3, term = (idx >> 10) & 1, gk = idx >> 11;
    int nb = p * 2 + (j >> 1), reg = j & 1;
    int n = nw * 32 + nb * 8 + (lane >> 2);
    int k = gk * 16 + reg * 8 + 2 * (lane & 3);
    float v0 = (k < 128) ? wl[n * 128 + k] : wr[n * 128 + (k - 128)];
    float v1 = (k + 1 < 128) ? wl[n * 128 + k + 1] : wr[n * 128 + (k + 1 - 128)];
    __nv_bfloat162 h2 = __float22bfloat162_rn(make_float2(v0, v1));
    if (term == 0) {
        bp[idx] = *(uint32_t*)&h2;
    } else {
        float r0 = v0 - __low2float(h2);
        float r1 = v1 - __high2float(h2);
        __nv_bfloat162 l2 = __float22bfloat162_rn(make_float2(r0, r1));
        bp[idx] = *(uint32_t*)&l2;
    }
}

// ===================== aggregation: lane-parallel index fetch + shfl broadcast =====================
__global__ void agg_kernel(const uint2* __restrict__ xp, float4* __restrict__ out4) {
    int gw = (blockIdx.x * blockDim.x + threadIdx.x) >> 5;
    int lane = threadIdx.x & 31;
    if (gw >= NN) return;
    int beg = g_offsets[gw], end = g_offsets[gw + 1];
    float a0 = 0.f, a1 = 0.f, a2 = 0.f, a3 = 0.f;
    for (int p = beg; p < end; p += 32) {
        int n = end - p; if (n > 32) n = 32;
        int idx = (p + lane < end) ? g_sorted[p + lane] : 0;
        int j = 0;
        for (; j + 4 <= n; j += 4) {
            int s0 = __shfl_sync(~0u, idx, j);
            int s1 = __shfl_sync(~0u, idx, j + 1);
            int s2 = __shfl_sync(~0u, idx, j + 2);
            int s3 = __shfl_sync(~0u, idx, j + 3);
            uint2 u0 = __ldg(&xp[(size_t)s0 * 32 + lane]);
            uint2 u1 = __ldg(&xp[(size_t)s1 * 32 + lane]);
            uint2 u2 = __ldg(&xp[(size_t)s2 * 32 + lane]);
            uint2 u3 = __ldg(&xp[(size_t)s3 * 32 + lane]);
            float2 f;
            f = __bfloat1622float2(*(__nv_bfloat162*)&u0.x); a0 += f.x; a1 += f.y;
            f = __bfloat1622float2(*(__nv_bfloat162*)&u0.y); a2 += f.x; a3 += f.y;
            f = __bfloat1622float2(*(__nv_bfloat162*)&u1.x); a0 += f.x; a1 += f.y;
            f = __bfloat1622float2(*(__nv_bfloat162*)&u1.y); a2 += f.x; a3 += f.y;
            f = __bfloat1622float2(*(__nv_bfloat162*)&u2.x); a0 += f.x; a1 += f.y;
            f = __bfloat1622float2(*(__nv_bfloat162*)&u2.y); a2 += f.x; a3 += f.y;
            f = __bfloat1622float2(*(__nv_bfloat162*)&u3.x); a0 += f.x; a1 += f.y;
            f = __bfloat1622float2(*(__nv_bfloat162*)&u3.y); a2 += f.x; a3 += f.y;
        }
        for (; j < n; j++) {
            int s = __shfl_sync(~0u, idx, j);
            uint2 u = __ldg(&xp[(size_t)s * 32 + lane]);
            float2 f;
            f = __bfloat1622float2(*(__nv_bfloat162*)&u.x); a0 += f.x; a1 += f.y;
            f = __bfloat1622float2(*(__nv_bfloat162*)&u.y); a2 += f.x; a3 += f.y;
        }
    }
    float inv = (end > beg) ? 1.0f / (float)(end - beg) : 0.0f;
    out4[(size_t)gw * 32 + lane] = make_float4(a0 * inv, a1 * inv, a2 * inv, a3 * inv);
}

// ===================== mma.sync GEMM =====================
// MODE 0: C fp32 + bf16 hi-plane out.  MODE 1: fused outproj (Out[n][4]).
#define AROW 144
#define SM_AHI  0
#define SM_ALO  18432
#define SM_BIAS 36864
#define SM_WOUT 37376
#define SM_RACC 39424
#define GEMM_SMEM 41472

__device__ __forceinline__ uint32_t smem_u32(const void* p) {
    uint32_t a;
    asm("{ .reg .u64 t; cvta.to.shared.u64 t, %1; cvt.u32.u64 %0, t; }" : "=r"(a) : "l"(p));
    return a;
}
__device__ __forceinline__ void ldm_x4(uint32_t* r, uint32_t addr) {
    asm volatile("ldmatrix.sync.aligned.m8n8.x4.shared.b16 {%0,%1,%2,%3}, [%4];"
                 : "=r"(r[0]), "=r"(r[1]), "=r"(r[2]), "=r"(r[3]) : "r"(addr));
}
__device__ __forceinline__ void mma_bf16(float* d, const uint32_t* a, uint32_t b0, uint32_t b1) {
    asm volatile("mma.sync.aligned.m16n8k16.row.col.f32.bf16.bf16.f32 "
                 "{%0,%1,%2,%3}, {%4,%5,%6,%7}, {%8,%9}, {%0,%1,%2,%3};"
                 : "+f"(d[0]), "+f"(d[1]), "+f"(d[2]), "+f"(d[3])
                 : "r"(a[0]), "r"(a[1]), "r"(a[2]), "r"(a[3]), "r"(b0), "r"(b1));
}

template <int MODE>
__global__ __launch_bounds__(256, 2) void gemm_mma_kernel(
    const float* __restrict__ A0, const float* __restrict__ A1,
    const uint32_t* __restrict__ Bp, const float* __restrict__ bias,
    float* __restrict__ C, uint32_t* __restrict__ Chp,
    const float* __restrict__ wout, const float* __restrict__ bout,
    float* __restrict__ Out)
{
    extern __shared__ char smem[];
    uint32_t sb = smem_u32(smem);
    int t = threadIdx.x, wid = t >> 5, lane = t & 31;
    int mw = wid >> 2, nw = wid & 3;      // warp grid 2 x 4

    if (t < 128) ((float*)(smem + SM_BIAS))[t] = bias[t];
    if (MODE == 1) {
        for (int i = t; i < 512; i += 256) ((float*)(smem + SM_WOUT))[i] = wout[i];
    }

    int frow = t >> 1, fh = t & 1;
    int lrow = (lane & 7) + ((lane >> 3) & 1) * 8;
    int lkb  = (lane >> 4) * 16;
    const float* bsm = (const float*)(smem + SM_BIAS);
    const float* wsm = (const float*)(smem + SM_WOUT);
    float* racc = (float*)(smem + SM_RACC);
    const uint4* bfrag = (const uint4*)(Bp) + ((nw * 2) * 128 + lane * 4) / 4;

    for (int tile = blockIdx.x; tile < TILES; tile += gridDim.x) {
        float acc[4][4][4];
        #pragma unroll
        for (int m = 0; m < 4; m++)
            #pragma unroll
            for (int nb = 0; nb < 4; nb++)
                #pragma unroll
                for (int r = 0; r < 4; r++) acc[m][nb][r] = 0.f;
        if (MODE == 1) {
            for (int i = t; i < 512; i += 256) racc[i] = 0.f;
        }

        int grow = tile * 128 + frow;
        bool rv = grow < NN;

        #pragma unroll 1
        for (int c = 0; c < 4; c++) {            // K chunks of 64
            __syncthreads();                     // prev ldmatrix done + racc zero visible
            {
                const float* As = (c < 2) ? A0 : A1;
                const float4* ap = (const float4*)As + (size_t)grow * 32 + ((c & 1) * 16 + fh * 8);
                float4 v[8];
                if (rv) {
                    #pragma unroll
                    for (int i = 0; i < 8; i++) v[i] = __ldg(ap + i);
                } else {
                    #pragma unroll
                    for (int i = 0; i < 8; i++) v[i] = make_float4(0.f, 0.f, 0.f, 0.f);
                }
                const float* vf = (const float*)v;
                uint32_t hw[16], lw[16];
                #pragma unroll
                for (int i = 0; i < 16; i++) {
                    float f0 = vf[2 * i], f1 = vf[2 * i + 1];
                    __nv_bfloat162 h2 = __float22bfloat162_rn(make_float2(f0, f1));
                    float r0 = f0 - __low2float(h2);
                    float r1 = f1 - __high2float(h2);
                    __nv_bfloat162 l2 = __float22bfloat162_rn(make_float2(r0, r1));
                    hw[i] = *(uint32_t*)&h2;
                    lw[i] = *(uint32_t*)&l2;
                }
                char* hb = smem + SM_AHI + frow * AROW + fh * 64;
                char* lb = smem + SM_ALO + frow * AROW + fh * 64;
                #pragma unroll
                for (int q = 0; q < 4; q++) {
                    *(uint4*)(hb + q * 16) = make_uint4(hw[4*q], hw[4*q+1], hw[4*q+2], hw[4*q+3]);
                    *(uint4*)(lb + q * 16) = make_uint4(lw[4*q], lw[4*q+1], lw[4*q+2], lw[4*q+3]);
                }
            }
            __syncthreads();
            #pragma unroll
            for (int ks = 0; ks < 4; ks++) {
                int gk = c * 4 + ks;
                const uint4* bgk = bfrag + (size_t)gk * 512;
                uint4 bh0 = __ldg(bgk + 0);
                uint4 bh1 = __ldg(bgk + 32);
                uint4 bl0 = __ldg(bgk + 256);
                uint4 bl1 = __ldg(bgk + 288);
                uint32_t bh[4][2] = {{bh0.x, bh0.y}, {bh0.z, bh0.w}, {bh1.x, bh1.y}, {bh1.z, bh1.w}};
                uint32_t bl[4][2] = {{bl0.x, bl0.y}, {bl0.z, bl0.w}, {bl1.x, bl1.y}, {bl1.z, bl1.w}};
                #pragma unroll
                for (int m = 0; m < 4; m++) {
                    uint32_t ah[4], al[4];
                    uint32_t rbase = sb + (uint32_t)((mw * 64 + m * 16 + lrow) * AROW + ks * 32 + lkb);
                    ldm_x4(ah, rbase + SM_AHI);
                    ldm_x4(al, rbase + SM_ALO);
                    #pragma unroll
                    for (int nb = 0; nb < 4; nb++) {
                        mma_bf16(acc[m][nb], ah, bh[nb][0], bh[nb][1]);
                        mma_bf16(acc[m][nb], al, bh[nb][0], bh[nb][1]);
                        mma_bf16(acc[m][nb], ah, bl[nb][0], bl[nb][1]);
                    }
                }
            }
        }
        // ---- epilogue ----
        if (MODE == 0) {
            #pragma unroll
            for (int m = 0; m < 4; m++) {
                int orow0 = tile * 128 + mw * 64 + m * 16 + (lane >> 2);
                #pragma unroll
                for (int nb = 0; nb < 4; nb++) {
                    int ocol = nw * 32 + nb * 8 + 2 * (lane & 3);
                    float b0 = bsm[ocol], b1 = bsm[ocol + 1];
                    if (orow0 < NN) {
                        float2 o = make_float2(fmaxf(acc[m][nb][0] + b0, 0.f),
                                               fmaxf(acc[m][nb][1] + b1, 0.f));
                        *(float2*)&C[(size_t)orow0 * 128 + ocol] = o;
                        __nv_bfloat162 hp = __float22bfloat162_rn(o);
                        Chp[(size_t)orow0 * 64 + (ocol >> 1)] = *(uint32_t*)&hp;
                    }
                    if (orow0 + 8 < NN) {
                        float2 o = make_float2(fmaxf(acc[m][nb][2] + b0, 0.f),
                                               fmaxf(acc[m][nb][3] + b1, 0.f));
                        *(float2*)&C[(size_t)(orow0 + 8) * 128 + ocol] = o;
                        __nv_bfloat162 hp = __float22bfloat162_rn(o);
                        Chp[(size_t)(orow0 + 8) * 64 + (ocol >> 1)] = *(uint32_t*)&hp;
                    }
                }
            }
        } else {
            // fused outproj: Out[r][j] = sum_c relu(acc+bias)[r][c] * wout[j][c] + bout[j]
            #pragma unroll
            for (int m = 0; m < 4; m++) {
                float pj0[4] = {0.f, 0.f, 0.f, 0.f};
                float pj1[4] = {0.f, 0.f, 0.f, 0.f};
                #pragma unroll
                for (int nb = 0; nb < 4; nb++) {
                    int ocol = nw * 32 + nb * 8 + 2 * (lane & 3);
                    float b0 = bsm[ocol], b1 = bsm[ocol + 1];
                    float v0 = fmaxf(acc[m][nb][0] + b0, 0.f);
                    float v1 = fmaxf(acc[m][nb][1] + b1, 0.f);
                    float v2 = fmaxf(acc[m][nb][2] + b0, 0.f);
                    float v3 = fmaxf(acc[m][nb][3] + b1, 0.f);
                    #pragma unroll
                    for (int j = 0; j < 4; j++) {
                        float w0 = wsm[j * 128 + ocol], w1 = wsm[j * 128 + ocol + 1];
                        pj0[j] += v0 * w0 + v1 * w1;
                        pj1[j] += v2 * w0 + v3 * w1;
                    }
                }
                #pragma unroll
                for (int j = 0; j < 4; j++) {
                    pj0[j] += __shfl_xor_sync(~0u, pj0[j], 1);
                    pj0[j] += __shfl_xor_sync(~0u, pj0[j], 2);
                    pj1[j] += __shfl_xor_sync(~0u, pj1[j], 1);
                    pj1[j] += __shfl_xor_sync(~0u, pj1[j], 2);
                }
                if ((lane & 3) == 0) {
                    int lr = mw * 64 + m * 16 + (lane >> 2);
                    #pragma unroll
                    for (int j = 0; j < 4; j++) {
                        atomicAdd(&racc[lr * 4 + j], pj0[j]);
                        atomicAdd(&racc[(lr + 8) * 4 + j], pj1[j]);
                    }
                }
            }
            __syncthreads();
            if (t < 128) {
                int orow = tile * 128 + t;
                if (orow < NN) {
                    float4 o;
                    o.x = racc[t * 4 + 0] + __ldg(&bout[0]);
                    o.y = racc[t * 4 + 1] + __ldg(&bout[1]);
                    o.z = racc[t * 4 + 2] + __ldg(&bout[2]);
                    o.w = racc[t * 4 + 3] + __ldg(&bout[3]);
                    *(float4*)&Out[(size_t)orow * 4] = o;
                }
            }
            __syncthreads();   // protect racc re-zero next tile
        }
    }
}

// ===================== launch =====================
extern "C" void kernel_launch(void* const* d_in, const int* in_sizes, int n_in,
                              void* d_out, int out_size) {
    const float* x    = (const float*)d_in[0];
    const int*   ei   = (const int*)d_in[1];
    const float* w1l  = (const float*)d_in[2];
    const float* b1l  = (const float*)d_in[3];
    const float* w1r  = (const float*)d_in[4];
    const float* w2l  = (const float*)d_in[5];
    const float* b2l  = (const float*)d_in[6];
    const float* w2r  = (const float*)d_in[7];
    const float* wout = (const float*)d_in[8];
    const float* bout = (const float*)d_in[9];
    float* out = (float*)d_out;

    int E = in_sizes[1] / 2;
    const int* src = ei;
    const int* dst = ei + E;

    uint2 *xh, *h1h;
    float *mean, *h1;
    uint32_t *bp1, *bp2;
    cudaGetSymbolAddress((void**)&xh, g_xh);
    cudaGetSymbolAddress((void**)&h1h, g_h1h);
    cudaGetSymbolAddress((void**)&mean, g_mean);
    cudaGetSymbolAddress((void**)&h1, g_h1);
    cudaGetSymbolAddress((void**)&bp1, g_bp1);
    cudaGetSymbolAddress((void**)&bp2, g_bp2);

    cudaFuncSetAttribute(gemm_mma_kernel<0>, cudaFuncAttributeMaxDynamicSharedMemorySize, GEMM_SMEM);
    cudaFuncSetAttribute(gemm_mma_kernel<1>, cudaFuncAttributeMaxDynamicSharedMemorySize, GEMM_SMEM);

    int n4 = NN * 32;
    int aggBlocks = (NN * 32 + 255) / 256;
    int nseg = (NN + 1023) / 1024;   // 98

    // CSR build (hist fused with x->bf16 plane; 3-phase coalesced scan)
    hist_tobf16_kernel<<<2048, 256>>>(dst, E, (const float4*)x, xh, n4);
    scan_local_kernel<<<nseg, 1024>>>();
    scan_bsum_kernel<<<1, 128>>>(nseg);
    scan_add_kernel<<<(NN + 255) / 256, 256>>>();
    scatter_kernel<<<2048, 256>>>(src, dst, E);

    // layer 1
    agg_kernel<<<aggBlocks, 256>>>(xh, (float4*)mean);
    pack_both_kernel<<<256, 256>>>(w1l, w1r, w2l, w2r, bp1, bp2);
    gemm_mma_kernel<0><<<296, 256, GEMM_SMEM>>>(mean, x, bp1, b1l,
                                                h1, (uint32_t*)h1h, nullptr, nullptr, nullptr);
    // layer 2 (+ fused output projection)
    agg_kernel<<<aggBlocks, 256>>>(h1h, (float4*)mean);
    gemm_mma_kernel<1><<<296, 256, GEMM_SMEM>>>(mean, h1, bp2, b2l,
                                                nullptr, nullptr, wout, bout, out);
}